// round 14
// baseline (speedup 1.0000x reference)
#include <cuda_runtime.h>
#include <cstdint>
#include <cstddef>

#define NN 1023
#define DD 1024
#define BB 4
#define TT 8192
#define SST 44    // padded smem row stride (floats)
#define NBLK 592  // 4 blocks/SM x 148 SMs -- all co-resident (GB300 has 152 SMs)

__device__ __align__(16) float g_states[BB * NN * DD];   // node states, fp32 (raw proj for internal)
__device__ __align__(16) float g_mixture[BB * DD];
__device__ __align__(16) float g_mixpart[8][5][DD];      // [split][Z,a0..a3][d]
__device__ unsigned g_bar_cnt;                            // grid barrier arrive count
__device__ volatile unsigned g_bar_gen;                   // grid barrier generation

// ---------------------------------------------------------------------------
// Prep: blk < 2048 -> leaves mean-pool; else zero internal nodes 0..510.
// ---------------------------------------------------------------------------
__global__ void __launch_bounds__(256) prep_kernel(const float* __restrict__ x) {
    int blk = blockIdx.x;
    if (blk < 2048) {
        int b = blk >> 9;
        int l = blk & 511;
        int d4 = threadIdx.x;
        const float4* xp = reinterpret_cast<const float4*>(x)
                           + ((size_t)(b * TT + l * 8)) * 256 + d4;
        float sx = 0.f, sy = 0.f, sz = 0.f, sw = 0.f;
#pragma unroll
        for (int i = 0; i < 8; i++) {
            float4 v = xp[(size_t)i * 256];
            sx += v.x; sy += v.y; sz += v.z; sw += v.w;
        }
        float4 o;
        o.x = sx * 0.125f; o.y = sy * 0.125f; o.z = sz * 0.125f; o.w = sw * 0.125f;
        reinterpret_cast<float4*>(g_states)[((size_t)b * NN + 511 + l) * 256 + d4] = o;
    } else {
        int i = (blk - 2048) * 256 + threadIdx.x;
        if (i < 523264) {                     // 4 * 511*1024/4
            int b = i / 130816;               // 511*1024/4
            int r = i - b * 130816;
            reinterpret_cast<float4*>(g_states + (size_t)b * NN * DD)[r] =
                make_float4(0.f, 0.f, 0.f, 0.f);
        }
    }
}

// ---------------------------------------------------------------------------
// Fused tree kernel: all 9 levels in one launch; grid-wide generation barrier
// between levels (all NBLK blocks resident by construction). Tile body is the
// R12 GEMM: 128 threads, 2x2 warp grid (32x32 subtiles), tf32 mma, cp.async
// double-buffered, split-K via red.global.add.v2, lazy threshold in registers.
// ---------------------------------------------------------------------------
__device__ __forceinline__ void mma_tf32(float c[4], const unsigned a[4], const unsigned b[2]) {
    asm volatile(
        "mma.sync.aligned.m16n8k8.row.col.f32.tf32.tf32.f32 "
        "{%0,%1,%2,%3}, {%4,%5,%6,%7}, {%8,%9}, {%0,%1,%2,%3};\n"
        : "+f"(c[0]), "+f"(c[1]), "+f"(c[2]), "+f"(c[3])
        : "r"(a[0]), "r"(a[1]), "r"(a[2]), "r"(a[3]),
          "r"(b[0]), "r"(b[1]));
}

__device__ __forceinline__ void red_add_v2(float* addr, float a, float b) {
    asm volatile("red.global.add.v2.f32 [%0], {%1, %2};\n"
                 :: "l"(addr), "f"(a), "f"(b) : "memory");
}

__device__ __forceinline__ unsigned smem_u32(const void* p) {
    return (unsigned)__cvta_generic_to_shared(p);
}

__device__ __forceinline__ void grid_barrier() {
    __syncthreads();
    if (threadIdx.x == 0) {
        __threadfence();                       // order red.v2 / stores before arrive
        unsigned gen = g_bar_gen;
        unsigned old = atomicAdd(&g_bar_cnt, 1);
        if (old == NBLK - 1) {
            g_bar_cnt = 0;
            __threadfence();
            g_bar_gen = gen + 1;
        } else {
            while (g_bar_gen == gen) { __nanosleep(64); }
        }
    }
    __syncthreads();
}

__global__ void __launch_bounds__(128, 4) tree_fused_kernel(const float* __restrict__ W,
                                                            const float* __restrict__ bt) {
    __shared__ float As[2][64 * SST];
    __shared__ float Bs[2][64 * SST];
    __shared__ float tb[2][32];

    int tid = threadIdx.x;
    int warp = tid >> 5, lane = tid & 31;
    int wm = warp >> 1, wn = warp & 1;        // 2x2 warp grid, 32x32 per warp
    int g = lane >> 2, t4 = lane & 3;

    // split schedule by level (index = level): L8:4 L7:4 L6:8 L5:8 L4..L0:16
    const int Stab[9] = {16, 16, 16, 16, 16, 8, 8, 4, 4};

    for (int level = 8; level >= 0; --level) {
        int NL = 1 << level;
        int ls = NL - 1;
        int Mtot = NL * 4;
        int S = Stab[level];
        int Kslab = 2048 / S;
        int iters = Kslab >> 5;
        int mblocks = (Mtot + 63) >> 6;
        int ntiles = mblocks * 16 * S;
        const float* btc = (level == 8) ? nullptr : (bt + (size_t)(level + 1) * DD);

        for (int t = blockIdx.x; t < ntiles; t += NBLK) {
            int split = t / (mblocks * 16);
            int rem = t - split * mblocks * 16;
            int n0 = (rem & 15) * 64;
            int m0 = (rem >> 4) * 64;
            int kbeg = split * Kslab;

            float acc[2][4][4];
#pragma unroll
            for (int i = 0; i < 2; i++)
#pragma unroll
                for (int j = 0; j < 4; j++)
#pragma unroll
                    for (int k = 0; k < 4; k++) acc[i][j][k] = 0.f;

#define STAGE(buf, kg)                                                               \
    {                                                                                \
        _Pragma("unroll")                                                            \
        for (int q = 0; q < 4; q++) {                                                \
            int i = q * 128 + tid;                                                   \
            int r = i >> 3, c = i & 7;                                               \
            unsigned sa = smem_u32(&As[buf][r * SST + c * 4]);                       \
            int rg = m0 + r;                                                         \
            const float* pa = W;                                                     \
            int sz = 0;                                                              \
            if (rg < Mtot) {                                                         \
                int bb = rg >> level;                                                \
                int jj = rg & (NL - 1);                                              \
                pa = g_states + ((size_t)bb * NN + (2 * ls + 1) + 2 * jj) * DD       \
                     + (kg) + c * 4;                                                 \
                sz = 16;                                                             \
            }                                                                        \
            asm volatile("cp.async.cg.shared.global [%0], [%1], 16, %2;\n"           \
                         :: "r"(sa), "l"(pa), "r"(sz));                              \
            unsigned sb = smem_u32(&Bs[buf][r * SST + c * 4]);                       \
            const float* pb = W + (size_t)(n0 + r) * 2048 + (kg) + c * 4;            \
            asm volatile("cp.async.cg.shared.global [%0], [%1], 16;\n"               \
                         :: "r"(sb), "l"(pb));                                       \
        }                                                                            \
        if (btc && tid < 8) {                                                        \
            unsigned st = smem_u32(&tb[buf][tid * 4]);                               \
            const float* pt = btc + (((kg) & 1023) + tid * 4);                       \
            asm volatile("cp.async.ca.shared.global [%0], [%1], 16;\n"               \
                         :: "r"(st), "l"(pt));                                       \
        }                                                                            \
        asm volatile("cp.async.commit_group;\n");                                    \
    }

            STAGE(0, kbeg);

            for (int it = 0; it < iters; ++it) {
                int cur = it & 1;
                if (it + 1 < iters) {
                    STAGE(cur ^ 1, kbeg + (it + 1) * 32);
                    asm volatile("cp.async.wait_group 1;\n");
                } else {
                    asm volatile("cp.async.wait_group 0;\n");
                }
                __syncthreads();

#pragma unroll
                for (int kk = 0; kk < 32; kk += 8) {
                    unsigned a[2][4], bf[4][2];
                    if (btc) {
                        float thr_lo = tb[cur][kk + t4];
                        float thr_hi = tb[cur][kk + t4 + 4];
#pragma unroll
                        for (int i = 0; i < 2; i++) {
                            int rb = (wm * 32 + i * 16 + g) * SST + kk + t4;
                            float f0 = As[cur][rb];
                            float f1 = As[cur][rb + 8 * SST];
                            float f2 = As[cur][rb + 4];
                            float f3 = As[cur][rb + 8 * SST + 4];
                            a[i][0] = __float_as_uint(f0 > thr_lo ? f0 : 0.f);
                            a[i][1] = __float_as_uint(f1 > thr_lo ? f1 : 0.f);
                            a[i][2] = __float_as_uint(f2 > thr_hi ? f2 : 0.f);
                            a[i][3] = __float_as_uint(f3 > thr_hi ? f3 : 0.f);
                        }
                    } else {
#pragma unroll
                        for (int i = 0; i < 2; i++) {
                            int rb = (wm * 32 + i * 16 + g) * SST + kk + t4;
                            a[i][0] = __float_as_uint(As[cur][rb]);
                            a[i][1] = __float_as_uint(As[cur][rb + 8 * SST]);
                            a[i][2] = __float_as_uint(As[cur][rb + 4]);
                            a[i][3] = __float_as_uint(As[cur][rb + 8 * SST + 4]);
                        }
                    }
#pragma unroll
                    for (int j = 0; j < 4; j++) {
                        int rb = (wn * 32 + j * 8 + g) * SST + kk + t4;
                        bf[j][0] = __float_as_uint(Bs[cur][rb]);
                        bf[j][1] = __float_as_uint(Bs[cur][rb + 4]);
                    }
#pragma unroll
                    for (int i = 0; i < 2; i++)
#pragma unroll
                        for (int j = 0; j < 4; j++)
                            mma_tf32(acc[i][j], a[i], bf[j]);
                }
                __syncthreads();
            }
#undef STAGE

            // epilogue: split-K accumulate of RAW proj via vector red
#pragma unroll
            for (int i = 0; i < 2; i++) {
                int rg = m0 + wm * 32 + i * 16 + g;
#pragma unroll
                for (int j = 0; j < 4; j++) {
                    int col = n0 + wn * 32 + j * 8 + t4 * 2;
                    if (rg < Mtot) {
                        int bb = rg >> level, jj = rg & (NL - 1);
                        float* Crow = g_states + ((size_t)bb * NN + ls + jj) * DD;
                        red_add_v2(&Crow[col], acc[i][j][0], acc[i][j][1]);
                    }
                    int rg8 = rg + 8;
                    if (rg8 < Mtot) {
                        int bb = rg8 >> level, jj = rg8 & (NL - 1);
                        float* Crow = g_states + ((size_t)bb * NN + ls + jj) * DD;
                        red_add_v2(&Crow[col], acc[i][j][2], acc[i][j][3]);
                    }
                }
            }
        }

        grid_barrier();   // level L complete before level L-1 reads it
    }
}

// ---------------------------------------------------------------------------
// Mixture, two-stage, lazy spike threshold per node level.
// ---------------------------------------------------------------------------
__global__ void __launch_bounds__(512) mixture1_kernel(const float* __restrict__ nw,
                                                       const float* __restrict__ bt) {
    int ld = threadIdx.x & 31;
    int ln = threadIdx.x >> 5;
    int d  = blockIdx.x * 32 + ld;
    int sp = blockIdx.y;
    int nend = sp * 128 + 128;
    if (nend > NN) nend = NN;
    float Z = 0.f, a0 = 0.f, a1 = 0.f, a2 = 0.f, a3 = 0.f;
    for (int n = sp * 128 + ln; n < nend; n += 16) {
        float e = __expf(nw[n * DD + d]);
        float v0 = g_states[((size_t)0 * NN + n) * DD + d];
        float v1 = g_states[((size_t)1 * NN + n) * DD + d];
        float v2 = g_states[((size_t)2 * NN + n) * DD + d];
        float v3 = g_states[((size_t)3 * NN + n) * DD + d];
        if (n < 511) {
            int lv = 31 - __clz(n + 1);
            float thr = bt[lv * DD + d];
            v0 = v0 > thr ? v0 : 0.f;
            v1 = v1 > thr ? v1 : 0.f;
            v2 = v2 > thr ? v2 : 0.f;
            v3 = v3 > thr ? v3 : 0.f;
        }
        Z += e;
        a0 += e * v0; a1 += e * v1; a2 += e * v2; a3 += e * v3;
    }
    __shared__ float red[5][16][32];
    red[0][ln][ld] = Z;  red[1][ln][ld] = a0; red[2][ln][ld] = a1;
    red[3][ln][ld] = a2; red[4][ln][ld] = a3;
    __syncthreads();
    if (ln == 0) {
        float v[5];
#pragma unroll
        for (int k = 0; k < 5; k++) {
            float s = 0.f;
#pragma unroll
            for (int i = 0; i < 16; i++) s += red[k][i][ld];
            v[k] = s;
        }
#pragma unroll
        for (int k = 0; k < 5; k++) g_mixpart[sp][k][d] = v[k];
    }
}

__global__ void __launch_bounds__(256) mixture2_kernel() {
    int d = blockIdx.x * 256 + threadIdx.x;
    float Z = 0.f, a0 = 0.f, a1 = 0.f, a2 = 0.f, a3 = 0.f;
#pragma unroll
    for (int sp = 0; sp < 8; sp++) {
        Z  += g_mixpart[sp][0][d];
        a0 += g_mixpart[sp][1][d];
        a1 += g_mixpart[sp][2][d];
        a2 += g_mixpart[sp][3][d];
        a3 += g_mixpart[sp][4][d];
    }
    float inv = 1.f / Z;
    g_mixture[0 * DD + d] = a0 * inv;
    g_mixture[1 * DD + d] = a1 * inv;
    g_mixture[2 * DD + d] = a2 * inv;
    g_mixture[3 * DD + d] = a3 * inv;
}

// ---------------------------------------------------------------------------
// Final: out = RMSNorm(x + mixture[b]) * rms_w, 8 rows per block.
// ---------------------------------------------------------------------------
__global__ void __launch_bounds__(256) final_kernel(const float* __restrict__ x,
                                                    const float* __restrict__ rms_w,
                                                    float* __restrict__ out) {
    int blk = blockIdx.x;
    int b  = blk >> 10;
    int t0 = (blk & 1023) * 8;
    int tid = threadIdx.x;
    int lane = tid & 31, warp = tid >> 5;

    __shared__ float4 smix[256];
    __shared__ float4 srw[256];
    __shared__ float  sred[8];

    smix[tid] = reinterpret_cast<const float4*>(g_mixture + b * DD)[tid];
    srw[tid]  = reinterpret_cast<const float4*>(rms_w)[tid];
    __syncthreads();
    float4 mix = smix[tid], rw = srw[tid];

    const float4* xb = reinterpret_cast<const float4*>(x) + ((size_t)(b * TT + t0)) * 256;
    float4*       ob = reinterpret_cast<float4*>(out)     + ((size_t)(b * TT + t0)) * 256;

    for (int r = 0; r < 8; r++) {
        float4 v = xb[(size_t)r * 256 + tid];
        v.x += mix.x; v.y += mix.y; v.z += mix.z; v.w += mix.w;
        float ss = v.x * v.x + v.y * v.y + v.z * v.z + v.w * v.w;
#pragma unroll
        for (int o = 16; o > 0; o >>= 1) ss += __shfl_xor_sync(0xffffffffu, ss, o);
        __syncthreads();
        if (lane == 0) sred[warp] = ss;
        __syncthreads();
        float tot = 0.f;
#pragma unroll
        for (int i = 0; i < 8; i++) tot += sred[i];
        float inv = rsqrtf(tot * (1.0f / 1024.0f) + 1.1920929e-7f);
        float4 o4;
        o4.x = v.x * rw.x * inv; o4.y = v.y * rw.y * inv;
        o4.z = v.z * rw.z * inv; o4.w = v.w * rw.w * inv;
        ob[(size_t)r * 256 + tid] = o4;
    }
}

// ---------------------------------------------------------------------------
// launch: prep -> fused tree (1 kernel, 9 levels) -> mixture -> final
// 5 launches total.
// ---------------------------------------------------------------------------
extern "C" void kernel_launch(void* const* d_in, const int* in_sizes, int n_in,
                              void* d_out, int out_size) {
    const float* x     = (const float*)d_in[0];
    const float* W     = (const float*)d_in[1];
    const float* nw    = (const float*)d_in[2];
    const float* bt    = (const float*)d_in[3];
    const float* rms_w = (const float*)d_in[5];   // as_w (d_in[4]) unused (×0.0)
    float* out = (float*)d_out;

    prep_kernel<<<4092, 256>>>(x);            // leaves + zero internal nodes
    tree_fused_kernel<<<NBLK, 128>>>(W, bt);  // all 9 levels, grid barriers inside
    mixture1_kernel<<<dim3(32, 8), 512>>>(nw, bt);
    mixture2_kernel<<<4, 256>>>();
    final_kernel<<<4096, 256>>>(x, rms_w, out);
}

// round 15
// speedup vs baseline: 1.2381x; 1.2381x over previous
#include <cuda_runtime.h>
#include <cstdint>
#include <cstddef>

#define NN 1023
#define DD 1024
#define BB 4
#define TT 8192
#define SST 44    // padded smem row stride (floats)
#define NT  64    // tail kernel persistent blocks (all co-resident)

__device__ __align__(16) float g_states[BB * NN * DD];   // node states, fp32 (raw proj for internal)
__device__ __align__(16) float g_mixture[BB * DD];
__device__ __align__(16) float g_mixpart[8][5][DD];      // [split][Z,a0..a3][d]
__device__ int g_any6;                                   // 1 if any L6 raw proj exceeds bt[6]
__device__ unsigned g_bar_cnt;
__device__ volatile unsigned g_bar_gen;

// ---------------------------------------------------------------------------
// Prep: blk < 2048 -> leaves mean-pool; else zero internal nodes 0..510.
// Also resets the L6 flag and tail barrier state each call (graph-replay safe).
// ---------------------------------------------------------------------------
__global__ void __launch_bounds__(256) prep_kernel(const float* __restrict__ x) {
    int blk = blockIdx.x;
    if (blk == 0 && threadIdx.x == 0) { g_any6 = 0; g_bar_cnt = 0; g_bar_gen = 0; }
    if (blk < 2048) {
        int b = blk >> 9;
        int l = blk & 511;
        int d4 = threadIdx.x;
        const float4* xp = reinterpret_cast<const float4*>(x)
                           + ((size_t)(b * TT + l * 8)) * 256 + d4;
        float sx = 0.f, sy = 0.f, sz = 0.f, sw = 0.f;
#pragma unroll
        for (int i = 0; i < 8; i++) {
            float4 v = xp[(size_t)i * 256];
            sx += v.x; sy += v.y; sz += v.z; sw += v.w;
        }
        float4 o;
        o.x = sx * 0.125f; o.y = sy * 0.125f; o.z = sz * 0.125f; o.w = sw * 0.125f;
        reinterpret_cast<float4*>(g_states)[((size_t)b * NN + 511 + l) * 256 + d4] = o;
    } else {
        int i = (blk - 2048) * 256 + threadIdx.x;
        if (i < 523264) {                     // 4 * 511*1024/4
            int b = i / 130816;               // 511*1024/4
            int r = i - b * 130816;
            reinterpret_cast<float4*>(g_states + (size_t)b * NN * DD)[r] =
                make_float4(0.f, 0.f, 0.f, 0.f);
        }
    }
}

// ---------------------------------------------------------------------------
// Shared GEMM machinery (R12 tile body: 128 thr, 2x2 warps, 64x64x32 tiles).
// ---------------------------------------------------------------------------
__device__ __forceinline__ void mma_tf32(float c[4], const unsigned a[4], const unsigned b[2]) {
    asm volatile(
        "mma.sync.aligned.m16n8k8.row.col.f32.tf32.tf32.f32 "
        "{%0,%1,%2,%3}, {%4,%5,%6,%7}, {%8,%9}, {%0,%1,%2,%3};\n"
        : "+f"(c[0]), "+f"(c[1]), "+f"(c[2]), "+f"(c[3])
        : "r"(a[0]), "r"(a[1]), "r"(a[2]), "r"(a[3]),
          "r"(b[0]), "r"(b[1]));
}

__device__ __forceinline__ void red_add_v2(float* addr, float a, float b) {
    asm volatile("red.global.add.v2.f32 [%0], {%1, %2};\n"
                 :: "l"(addr), "f"(a), "f"(b) : "memory");
}

__device__ __forceinline__ unsigned smem_u32(const void* p) {
    return (unsigned)__cvta_generic_to_shared(p);
}

// stage one 64x32 A tile + 64x32 W tile (+ child thresholds) into buffer `buf`
#define STAGE(buf, kg)                                                               \
    {                                                                                \
        _Pragma("unroll")                                                            \
        for (int q = 0; q < 4; q++) {                                                \
            int i = q * 128 + tid;                                                   \
            int r = i >> 3, c = i & 7;                                               \
            unsigned sa = smem_u32(&As[buf][r * SST + c * 4]);                       \
            int rg = m0 + r;                                                         \
            const float* pa = W;                                                     \
            int sz = 0;                                                              \
            if (rg < Mtot) {                                                         \
                int bb = rg >> level;                                                \
                int jj = rg & (NL - 1);                                              \
                pa = g_states + ((size_t)bb * NN + (2 * ls + 1) + 2 * jj) * DD       \
                     + (kg) + c * 4;                                                 \
                sz = 16;                                                             \
            }                                                                        \
            asm volatile("cp.async.cg.shared.global [%0], [%1], 16, %2;\n"           \
                         :: "r"(sa), "l"(pa), "r"(sz));                              \
            unsigned sb = smem_u32(&Bs[buf][r * SST + c * 4]);                       \
            const float* pb = W + (size_t)(n0 + r) * 2048 + (kg) + c * 4;            \
            asm volatile("cp.async.cg.shared.global [%0], [%1], 16;\n"               \
                         :: "r"(sb), "l"(pb));                                       \
        }                                                                            \
        if (btc && tid < 8) {                                                        \
            unsigned st = smem_u32(&tb[buf][tid * 4]);                               \
            const float* pt = btc + (((kg) & 1023) + tid * 4);                       \
            asm volatile("cp.async.ca.shared.global [%0], [%1], 16;\n"               \
                         :: "r"(st), "l"(pt));                                       \
        }                                                                            \
        asm volatile("cp.async.commit_group;\n");                                    \
    }

// inner K-loop (double-buffered) accumulating into acc[2][4][4]
#define KLOOP(KBEG, ITERS)                                                           \
    STAGE(0, KBEG);                                                                  \
    for (int it = 0; it < (ITERS); ++it) {                                           \
        int cur = it & 1;                                                            \
        if (it + 1 < (ITERS)) {                                                      \
            STAGE(cur ^ 1, (KBEG) + (it + 1) * 32);                                  \
            asm volatile("cp.async.wait_group 1;\n");                                \
        } else {                                                                     \
            asm volatile("cp.async.wait_group 0;\n");                                \
        }                                                                            \
        __syncthreads();                                                             \
        _Pragma("unroll")                                                            \
        for (int kk = 0; kk < 32; kk += 8) {                                         \
            unsigned a[2][4], bf[4][2];                                              \
            if (btc) {                                                               \
                float thr_lo = tb[cur][kk + t4];                                     \
                float thr_hi = tb[cur][kk + t4 + 4];                                 \
                _Pragma("unroll")                                                    \
                for (int i = 0; i < 2; i++) {                                        \
                    int rb = (wm * 32 + i * 16 + g) * SST + kk + t4;                 \
                    float f0 = As[cur][rb];                                          \
                    float f1 = As[cur][rb + 8 * SST];                                \
                    float f2 = As[cur][rb + 4];                                      \
                    float f3 = As[cur][rb + 8 * SST + 4];                            \
                    a[i][0] = __float_as_uint(f0 > thr_lo ? f0 : 0.f);               \
                    a[i][1] = __float_as_uint(f1 > thr_lo ? f1 : 0.f);               \
                    a[i][2] = __float_as_uint(f2 > thr_hi ? f2 : 0.f);               \
                    a[i][3] = __float_as_uint(f3 > thr_hi ? f3 : 0.f);               \
                }                                                                    \
            } else {                                                                 \
                _Pragma("unroll")                                                    \
                for (int i = 0; i < 2; i++) {                                        \
                    int rb = (wm * 32 + i * 16 + g) * SST + kk + t4;                 \
                    a[i][0] = __float_as_uint(As[cur][rb]);                          \
                    a[i][1] = __float_as_uint(As[cur][rb + 8 * SST]);                \
                    a[i][2] = __float_as_uint(As[cur][rb + 4]);                      \
                    a[i][3] = __float_as_uint(As[cur][rb + 8 * SST + 4]);            \
                }                                                                    \
            }                                                                        \
            _Pragma("unroll")                                                        \
            for (int j = 0; j < 4; j++) {                                            \
                int rb = (wn * 32 + j * 8 + g) * SST + kk + t4;                      \
                bf[j][0] = __float_as_uint(Bs[cur][rb]);                             \
                bf[j][1] = __float_as_uint(Bs[cur][rb + 4]);                         \
            }                                                                        \
            _Pragma("unroll")                                                        \
            for (int i = 0; i < 2; i++)                                              \
                _Pragma("unroll")                                                    \
                for (int j = 0; j < 4; j++)                                          \
                    mma_tf32(acc[i][j], a[i], bf[j]);                                \
        }                                                                            \
        __syncthreads();                                                             \
    }

#define ZERO_ACC()                                                                   \
    _Pragma("unroll")                                                                \
    for (int i = 0; i < 2; i++)                                                      \
        _Pragma("unroll")                                                            \
        for (int j = 0; j < 4; j++)                                                  \
            _Pragma("unroll")                                                        \
            for (int k = 0; k < 4; k++) acc[i][j][k] = 0.f;

// ---------------------------------------------------------------------------
// Levels 8 and 7: split-K (S=4) with red.global.add.v2 epilogue (R12 body).
// ---------------------------------------------------------------------------
__global__ void __launch_bounds__(128) tree_gemm2_kernel(const float* __restrict__ W,
                                                         const float* __restrict__ btc,
                                                         int level, int ls, int NL,
                                                         int Kslab) {
    int split = blockIdx.z;
    int m0 = blockIdx.x * 64;
    int n0 = blockIdx.y * 64;
    int Mtot = NL * 4;
    int kbeg = split * Kslab;
    int iters = Kslab >> 5;

    __shared__ float As[2][64 * SST];
    __shared__ float Bs[2][64 * SST];
    __shared__ float tb[2][32];

    int tid = threadIdx.x;
    int warp = tid >> 5, lane = tid & 31;
    int wm = warp >> 1, wn = warp & 1;
    int g = lane >> 2, t4 = lane & 3;

    float acc[2][4][4];
    ZERO_ACC();
    KLOOP(kbeg, iters);

#pragma unroll
    for (int i = 0; i < 2; i++) {
        int rg = m0 + wm * 32 + i * 16 + g;
#pragma unroll
        for (int j = 0; j < 4; j++) {
            int col = n0 + wn * 32 + j * 8 + t4 * 2;
            if (rg < Mtot) {
                int bb = rg >> level, jj = rg & (NL - 1);
                float* Crow = g_states + ((size_t)bb * NN + ls + jj) * DD;
                red_add_v2(&Crow[col], acc[i][j][0], acc[i][j][1]);
            }
            int rg8 = rg + 8;
            if (rg8 < Mtot) {
                int bb = rg8 >> level, jj = rg8 & (NL - 1);
                float* Crow = g_states + ((size_t)bb * NN + ls + jj) * DD;
                red_add_v2(&Crow[col], acc[i][j][2], acc[i][j][3]);
            }
        }
    }
}

// ---------------------------------------------------------------------------
// Level 6: full-K (S=1), plain store, sets g_any6 if any raw proj > bt[6][d].
// grid (4, 16).
// ---------------------------------------------------------------------------
__global__ void __launch_bounds__(128) tree_l6_kernel(const float* __restrict__ W,
                                                      const float* __restrict__ bt) {
    const int level = 6, ls = 63, NL = 64, Mtot = 256;
    const float* btc = bt + 7 * DD;          // children = level 7
    int m0 = blockIdx.x * 64;
    int n0 = blockIdx.y * 64;

    __shared__ float As[2][64 * SST];
    __shared__ float Bs[2][64 * SST];
    __shared__ float tb[2][32];

    int tid = threadIdx.x;
    int warp = tid >> 5, lane = tid & 31;
    int wm = warp >> 1, wn = warp & 1;
    int g = lane >> 2, t4 = lane & 3;

    float acc[2][4][4];
    ZERO_ACC();
    KLOOP(0, 64);

    const float* bt6 = bt + 6 * DD;
    int any = 0;
#pragma unroll
    for (int i = 0; i < 2; i++) {
        int rg = m0 + wm * 32 + i * 16 + g;
#pragma unroll
        for (int j = 0; j < 4; j++) {
            int col = n0 + wn * 32 + j * 8 + t4 * 2;
            float thr0 = bt6[col], thr1 = bt6[col + 1];
            {
                int bb = rg >> level, jj = rg & (NL - 1);
                float* Crow = g_states + ((size_t)bb * NN + ls + jj) * DD;
                Crow[col]     = acc[i][j][0];
                Crow[col + 1] = acc[i][j][1];
                any |= (acc[i][j][0] > thr0) | (acc[i][j][1] > thr1);
            }
            {
                int rg8 = rg + 8;
                int bb = rg8 >> level, jj = rg8 & (NL - 1);
                float* Crow = g_states + ((size_t)bb * NN + ls + jj) * DD;
                Crow[col]     = acc[i][j][2];
                Crow[col + 1] = acc[i][j][3];
                any |= (acc[i][j][2] > thr0) | (acc[i][j][3] > thr1);
            }
        }
    }
    if (__syncthreads_or(any)) {
        if (tid == 0) g_any6 = 1;
    }
}

// ---------------------------------------------------------------------------
// Tail: levels 5..0. If no L6 value passed its threshold, all remaining levels
// are exactly zero (states pre-zeroed by prep) -> return immediately.
// Rare path: compute levels sequentially with grid barriers (NT blocks, all
// resident), full-K, plain stores.
// ---------------------------------------------------------------------------
__device__ __forceinline__ void tail_barrier() {
    __syncthreads();
    if (threadIdx.x == 0) {
        __threadfence();
        unsigned gen = g_bar_gen;
        unsigned old = atomicAdd(&g_bar_cnt, 1);
        if (old == NT - 1) {
            g_bar_cnt = 0;
            __threadfence();
            g_bar_gen = gen + 1;
        } else {
            while (g_bar_gen == gen) { __nanosleep(64); }
        }
    }
    __syncthreads();
}

__global__ void __launch_bounds__(128) tree_tail_kernel(const float* __restrict__ W,
                                                        const float* __restrict__ bt) {
    if (g_any6 == 0) return;                 // expected path: everything below L6 is zero

    __shared__ float As[2][64 * SST];
    __shared__ float Bs[2][64 * SST];
    __shared__ float tb[2][32];

    int tid = threadIdx.x;
    int warp = tid >> 5, lane = tid & 31;
    int wm = warp >> 1, wn = warp & 1;
    int g = lane >> 2, t4 = lane & 3;

    for (int level = 5; level >= 0; --level) {
        int NL = 1 << level;
        int ls = NL - 1;
        int Mtot = NL * 4;
        int mblocks = (Mtot + 63) >> 6;
        int ntiles = mblocks * 16;
        const float* btc = bt + (size_t)(level + 1) * DD;

        for (int t = blockIdx.x; t < ntiles; t += NT) {
            int m0 = (t >> 4) * 64;
            int n0 = (t & 15) * 64;

            float acc[2][4][4];
            ZERO_ACC();
            KLOOP(0, 64);

#pragma unroll
            for (int i = 0; i < 2; i++) {
                int rg = m0 + wm * 32 + i * 16 + g;
#pragma unroll
                for (int j = 0; j < 4; j++) {
                    int col = n0 + wn * 32 + j * 8 + t4 * 2;
                    if (rg < Mtot) {
                        int bb = rg >> level, jj = rg & (NL - 1);
                        float* Crow = g_states + ((size_t)bb * NN + ls + jj) * DD;
                        Crow[col]     = acc[i][j][0];
                        Crow[col + 1] = acc[i][j][1];
                    }
                    int rg8 = rg + 8;
                    if (rg8 < Mtot) {
                        int bb = rg8 >> level, jj = rg8 & (NL - 1);
                        float* Crow = g_states + ((size_t)bb * NN + ls + jj) * DD;
                        Crow[col]     = acc[i][j][2];
                        Crow[col + 1] = acc[i][j][3];
                    }
                }
            }
        }
        tail_barrier();
    }
}

// ---------------------------------------------------------------------------
// Mixture, two-stage, lazy spike threshold per node level.
// ---------------------------------------------------------------------------
__global__ void __launch_bounds__(512) mixture1_kernel(const float* __restrict__ nw,
                                                       const float* __restrict__ bt) {
    int ld = threadIdx.x & 31;
    int ln = threadIdx.x >> 5;
    int d  = blockIdx.x * 32 + ld;
    int sp = blockIdx.y;
    int nend = sp * 128 + 128;
    if (nend > NN) nend = NN;
    float Z = 0.f, a0 = 0.f, a1 = 0.f, a2 = 0.f, a3 = 0.f;
    for (int n = sp * 128 + ln; n < nend; n += 16) {
        float e = __expf(nw[n * DD + d]);
        float v0 = g_states[((size_t)0 * NN + n) * DD + d];
        float v1 = g_states[((size_t)1 * NN + n) * DD + d];
        float v2 = g_states[((size_t)2 * NN + n) * DD + d];
        float v3 = g_states[((size_t)3 * NN + n) * DD + d];
        if (n < 511) {
            int lv = 31 - __clz(n + 1);
            float thr = bt[lv * DD + d];
            v0 = v0 > thr ? v0 : 0.f;
            v1 = v1 > thr ? v1 : 0.f;
            v2 = v2 > thr ? v2 : 0.f;
            v3 = v3 > thr ? v3 : 0.f;
        }
        Z += e;
        a0 += e * v0; a1 += e * v1; a2 += e * v2; a3 += e * v3;
    }
    __shared__ float red[5][16][32];
    red[0][ln][ld] = Z;  red[1][ln][ld] = a0; red[2][ln][ld] = a1;
    red[3][ln][ld] = a2; red[4][ln][ld] = a3;
    __syncthreads();
    if (ln == 0) {
        float v[5];
#pragma unroll
        for (int k = 0; k < 5; k++) {
            float s = 0.f;
#pragma unroll
            for (int i = 0; i < 16; i++) s += red[k][i][ld];
            v[k] = s;
        }
#pragma unroll
        for (int k = 0; k < 5; k++) g_mixpart[sp][k][d] = v[k];
    }
}

__global__ void __launch_bounds__(256) mixture2_kernel() {
    int d = blockIdx.x * 256 + threadIdx.x;
    float Z = 0.f, a0 = 0.f, a1 = 0.f, a2 = 0.f, a3 = 0.f;
#pragma unroll
    for (int sp = 0; sp < 8; sp++) {
        Z  += g_mixpart[sp][0][d];
        a0 += g_mixpart[sp][1][d];
        a1 += g_mixpart[sp][2][d];
        a2 += g_mixpart[sp][3][d];
        a3 += g_mixpart[sp][4][d];
    }
    float inv = 1.f / Z;
    g_mixture[0 * DD + d] = a0 * inv;
    g_mixture[1 * DD + d] = a1 * inv;
    g_mixture[2 * DD + d] = a2 * inv;
    g_mixture[3 * DD + d] = a3 * inv;
}

// ---------------------------------------------------------------------------
// Final: out = RMSNorm(x + mixture[b]) * rms_w, 8 rows per block.
// ---------------------------------------------------------------------------
__global__ void __launch_bounds__(256) final_kernel(const float* __restrict__ x,
                                                    const float* __restrict__ rms_w,
                                                    float* __restrict__ out) {
    int blk = blockIdx.x;
    int b  = blk >> 10;
    int t0 = (blk & 1023) * 8;
    int tid = threadIdx.x;
    int lane = tid & 31, warp = tid >> 5;

    __shared__ float4 smix[256];
    __shared__ float4 srw[256];
    __shared__ float  sred[8];

    smix[tid] = reinterpret_cast<const float4*>(g_mixture + b * DD)[tid];
    srw[tid]  = reinterpret_cast<const float4*>(rms_w)[tid];
    __syncthreads();
    float4 mix = smix[tid], rw = srw[tid];

    const float4* xb = reinterpret_cast<const float4*>(x) + ((size_t)(b * TT + t0)) * 256;
    float4*       ob = reinterpret_cast<float4*>(out)     + ((size_t)(b * TT + t0)) * 256;

    for (int r = 0; r < 8; r++) {
        float4 v = xb[(size_t)r * 256 + tid];
        v.x += mix.x; v.y += mix.y; v.z += mix.z; v.w += mix.w;
        float ss = v.x * v.x + v.y * v.y + v.z * v.z + v.w * v.w;
#pragma unroll
        for (int o = 16; o > 0; o >>= 1) ss += __shfl_xor_sync(0xffffffffu, ss, o);
        __syncthreads();
        if (lane == 0) sred[warp] = ss;
        __syncthreads();
        float tot = 0.f;
#pragma unroll
        for (int i = 0; i < 8; i++) tot += sred[i];
        float inv = rsqrtf(tot * (1.0f / 1024.0f) + 1.1920929e-7f);
        float4 o4;
        o4.x = v.x * rw.x * inv; o4.y = v.y * rw.y * inv;
        o4.z = v.z * rw.z * inv; o4.w = v.w * rw.w * inv;
        ob[(size_t)r * 256 + tid] = o4;
    }
}

// ---------------------------------------------------------------------------
// launch: prep -> L8 -> L7 -> L6(flag) -> tail(L5..L0, usually no-op)
//         -> mixture1 -> mixture2 -> final   (8 launches)
// ---------------------------------------------------------------------------
extern "C" void kernel_launch(void* const* d_in, const int* in_sizes, int n_in,
                              void* d_out, int out_size) {
    const float* x     = (const float*)d_in[0];
    const float* W     = (const float*)d_in[1];
    const float* nw    = (const float*)d_in[2];
    const float* bt    = (const float*)d_in[3];
    const float* rms_w = (const float*)d_in[5];   // as_w (d_in[4]) unused (×0.0)
    float* out = (float*)d_out;

    prep_kernel<<<4092, 256>>>(x);

    // L8: M=1024, S=4, A = leaves (no threshold)
    tree_gemm2_kernel<<<dim3(16, 16, 4), 128>>>(W, nullptr, 8, 255, 256, 512);
    // L7: M=512, S=4, children thresholds bt[8]
    tree_gemm2_kernel<<<dim3(8, 16, 4), 128>>>(W, bt + 8 * DD, 7, 127, 128, 512);
    // L6: full-K, plain store, sets g_any6
    tree_l6_kernel<<<dim3(4, 16), 128>>>(W, bt);
    // L5..L0: early-exit when L6 produced no spikes (the expected case)
    tree_tail_kernel<<<NT, 128>>>(W, bt);

    mixture1_kernel<<<dim3(32, 8), 512>>>(nw, bt);
    mixture2_kernel<<<4, 256>>>();
    final_kernel<<<4096, 256>>>(x, rms_w, out);
}

// round 16
// speedup vs baseline: 1.3559x; 1.0952x over previous
#include <cuda_runtime.h>
#include <cstdint>
#include <cstddef>

#define NN 1023
#define DD 1024
#define BB 4
#define TT 8192
#define SST 44    // padded smem row stride (floats)
#define NT  64    // tail kernel persistent blocks (all co-resident)

__device__ __align__(16) float g_states[BB * NN * DD];   // node states, fp32 (raw proj for internal)
__device__ __align__(16) float g_mixture[BB * DD];
__device__ __align__(16) float g_mixpart[8][5][DD];      // [split][Z,a0..a3][d]
__device__ int g_any6;                                   // 1 if any L6 raw proj exceeds bt[6]
__device__ unsigned g_bar_cnt;
__device__ volatile unsigned g_bar_gen;

// ---------------------------------------------------------------------------
// Prep: blk < 2048 -> leaves mean-pool; else zero internal nodes 0..510.
// Also resets the L6 flag and tail barrier state each call (graph-replay safe).
// ---------------------------------------------------------------------------
__global__ void __launch_bounds__(256) prep_kernel(const float* __restrict__ x) {
    int blk = blockIdx.x;
    if (blk == 0 && threadIdx.x == 0) { g_any6 = 0; g_bar_cnt = 0; g_bar_gen = 0; }
    if (blk < 2048) {
        int b = blk >> 9;
        int l = blk & 511;
        int d4 = threadIdx.x;
        const float4* xp = reinterpret_cast<const float4*>(x)
                           + ((size_t)(b * TT + l * 8)) * 256 + d4;
        float sx = 0.f, sy = 0.f, sz = 0.f, sw = 0.f;
#pragma unroll
        for (int i = 0; i < 8; i++) {
            float4 v = xp[(size_t)i * 256];
            sx += v.x; sy += v.y; sz += v.z; sw += v.w;
        }
        float4 o;
        o.x = sx * 0.125f; o.y = sy * 0.125f; o.z = sz * 0.125f; o.w = sw * 0.125f;
        reinterpret_cast<float4*>(g_states)[((size_t)b * NN + 511 + l) * 256 + d4] = o;
    } else {
        int i = (blk - 2048) * 256 + threadIdx.x;
        if (i < 523264) {                     // 4 * 511*1024/4
            int b = i / 130816;               // 511*1024/4
            int r = i - b * 130816;
            reinterpret_cast<float4*>(g_states + (size_t)b * NN * DD)[r] =
                make_float4(0.f, 0.f, 0.f, 0.f);
        }
    }
}

// ---------------------------------------------------------------------------
// Shared GEMM machinery (R12 tile body: 128 thr, 2x2 warps, 64x64x32 tiles).
// ---------------------------------------------------------------------------
__device__ __forceinline__ void mma_tf32(float c[4], const unsigned a[4], const unsigned b[2]) {
    asm volatile(
        "mma.sync.aligned.m16n8k8.row.col.f32.tf32.tf32.f32 "
        "{%0,%1,%2,%3}, {%4,%5,%6,%7}, {%8,%9}, {%0,%1,%2,%3};\n"
        : "+f"(c[0]), "+f"(c[1]), "+f"(c[2]), "+f"(c[3])
        : "r"(a[0]), "r"(a[1]), "r"(a[2]), "r"(a[3]),
          "r"(b[0]), "r"(b[1]));
}

__device__ __forceinline__ void red_add_v2(float* addr, float a, float b) {
    asm volatile("red.global.add.v2.f32 [%0], {%1, %2};\n"
                 :: "l"(addr), "f"(a), "f"(b) : "memory");
}

__device__ __forceinline__ unsigned smem_u32(const void* p) {
    return (unsigned)__cvta_generic_to_shared(p);
}

// stage one 64x32 A tile + 64x32 W tile (+ child thresholds) into buffer `buf`
#define STAGE(buf, kg)                                                               \
    {                                                                                \
        _Pragma("unroll")                                                            \
        for (int q = 0; q < 4; q++) {                                                \
            int i = q * 128 + tid;                                                   \
            int r = i >> 3, c = i & 7;                                               \
            unsigned sa = smem_u32(&As[buf][r * SST + c * 4]);                       \
            int rg = m0 + r;                                                         \
            const float* pa = W;                                                     \
            int sz = 0;                                                              \
            if (rg < Mtot) {                                                         \
                int bb = rg >> level;                                                \
                int jj = rg & (NL - 1);                                              \
                pa = g_states + ((size_t)bb * NN + (2 * ls + 1) + 2 * jj) * DD       \
                     + (kg) + c * 4;                                                 \
                sz = 16;                                                             \
            }                                                                        \
            asm volatile("cp.async.cg.shared.global [%0], [%1], 16, %2;\n"           \
                         :: "r"(sa), "l"(pa), "r"(sz));                              \
            unsigned sb = smem_u32(&Bs[buf][r * SST + c * 4]);                       \
            const float* pb = W + (size_t)(n0 + r) * 2048 + (kg) + c * 4;            \
            asm volatile("cp.async.cg.shared.global [%0], [%1], 16;\n"               \
                         :: "r"(sb), "l"(pb));                                       \
        }                                                                            \
        if (btc && tid < 8) {                                                        \
            unsigned st = smem_u32(&tb[buf][tid * 4]);                               \
            const float* pt = btc + (((kg) & 1023) + tid * 4);                       \
            asm volatile("cp.async.ca.shared.global [%0], [%1], 16;\n"               \
                         :: "r"(st), "l"(pt));                                       \
        }                                                                            \
        asm volatile("cp.async.commit_group;\n");                                    \
    }

// inner K-loop (double-buffered) accumulating into acc[2][4][4]
#define KLOOP(KBEG, ITERS)                                                           \
    STAGE(0, KBEG);                                                                  \
    for (int it = 0; it < (ITERS); ++it) {                                           \
        int cur = it & 1;                                                            \
        if (it + 1 < (ITERS)) {                                                      \
            STAGE(cur ^ 1, (KBEG) + (it + 1) * 32);                                  \
            asm volatile("cp.async.wait_group 1;\n");                                \
        } else {                                                                     \
            asm volatile("cp.async.wait_group 0;\n");                                \
        }                                                                            \
        __syncthreads();                                                             \
        _Pragma("unroll")                                                            \
        for (int kk = 0; kk < 32; kk += 8) {                                         \
            unsigned a[2][4], bf[4][2];                                              \
            if (btc) {                                                               \
                float thr_lo = tb[cur][kk + t4];                                     \
                float thr_hi = tb[cur][kk + t4 + 4];                                 \
                _Pragma("unroll")                                                    \
                for (int i = 0; i < 2; i++) {                                        \
                    int rb = (wm * 32 + i * 16 + g) * SST + kk + t4;                 \
                    float f0 = As[cur][rb];                                          \
                    float f1 = As[cur][rb + 8 * SST];                                \
                    float f2 = As[cur][rb + 4];                                      \
                    float f3 = As[cur][rb + 8 * SST + 4];                            \
                    a[i][0] = __float_as_uint(f0 > thr_lo ? f0 : 0.f);               \
                    a[i][1] = __float_as_uint(f1 > thr_lo ? f1 : 0.f);               \
                    a[i][2] = __float_as_uint(f2 > thr_hi ? f2 : 0.f);               \
                    a[i][3] = __float_as_uint(f3 > thr_hi ? f3 : 0.f);               \
                }                                                                    \
            } else {                                                                 \
                _Pragma("unroll")                                                    \
                for (int i = 0; i < 2; i++) {                                        \
                    int rb = (wm * 32 + i * 16 + g) * SST + kk + t4;                 \
                    a[i][0] = __float_as_uint(As[cur][rb]);                          \
                    a[i][1] = __float_as_uint(As[cur][rb + 8 * SST]);                \
                    a[i][2] = __float_as_uint(As[cur][rb + 4]);                      \
                    a[i][3] = __float_as_uint(As[cur][rb + 8 * SST + 4]);            \
                }                                                                    \
            }                                                                        \
            _Pragma("unroll")                                                        \
            for (int j = 0; j < 4; j++) {                                            \
                int rb = (wn * 32 + j * 8 + g) * SST + kk + t4;                      \
                bf[j][0] = __float_as_uint(Bs[cur][rb]);                             \
                bf[j][1] = __float_as_uint(Bs[cur][rb + 4]);                         \
            }                                                                        \
            _Pragma("unroll")                                                        \
            for (int i = 0; i < 2; i++)                                              \
                _Pragma("unroll")                                                    \
                for (int j = 0; j < 4; j++)                                          \
                    mma_tf32(acc[i][j], a[i], bf[j]);                                \
        }                                                                            \
        __syncthreads();                                                             \
    }

#define ZERO_ACC()                                                                   \
    _Pragma("unroll")                                                                \
    for (int i = 0; i < 2; i++)                                                      \
        _Pragma("unroll")                                                            \
        for (int j = 0; j < 4; j++)                                                  \
            _Pragma("unroll")                                                        \
            for (int k = 0; k < 4; k++) acc[i][j][k] = 0.f;

// ---------------------------------------------------------------------------
// Levels 8, 7, 6: split-K with red.global.add.v2 epilogue (R12 body).
// ---------------------------------------------------------------------------
__global__ void __launch_bounds__(128) tree_gemm2_kernel(const float* __restrict__ W,
                                                         const float* __restrict__ btc,
                                                         int level, int ls, int NL,
                                                         int Kslab) {
    int split = blockIdx.z;
    int m0 = blockIdx.x * 64;
    int n0 = blockIdx.y * 64;
    int Mtot = NL * 4;
    int kbeg = split * Kslab;
    int iters = Kslab >> 5;

    __shared__ float As[2][64 * SST];
    __shared__ float Bs[2][64 * SST];
    __shared__ float tb[2][32];

    int tid = threadIdx.x;
    int warp = tid >> 5, lane = tid & 31;
    int wm = warp >> 1, wn = warp & 1;
    int g = lane >> 2, t4 = lane & 3;

    float acc[2][4][4];
    ZERO_ACC();
    KLOOP(kbeg, iters);

#pragma unroll
    for (int i = 0; i < 2; i++) {
        int rg = m0 + wm * 32 + i * 16 + g;
#pragma unroll
        for (int j = 0; j < 4; j++) {
            int col = n0 + wn * 32 + j * 8 + t4 * 2;
            if (rg < Mtot) {
                int bb = rg >> level, jj = rg & (NL - 1);
                float* Crow = g_states + ((size_t)bb * NN + ls + jj) * DD;
                red_add_v2(&Crow[col], acc[i][j][0], acc[i][j][1]);
            }
            int rg8 = rg + 8;
            if (rg8 < Mtot) {
                int bb = rg8 >> level, jj = rg8 & (NL - 1);
                float* Crow = g_states + ((size_t)bb * NN + ls + jj) * DD;
                red_add_v2(&Crow[col], acc[i][j][2], acc[i][j][3]);
            }
        }
    }
}

// ---------------------------------------------------------------------------
// L6 flag scan: g_any6 = 1 if any L6 raw proj (nodes 63..126, all batches)
// exceeds bt[6][d]. 4*64*1024 floats = 65536 float4 -> 256 blocks x 256 thr.
// ---------------------------------------------------------------------------
__global__ void __launch_bounds__(256) l6_flag_kernel(const float* __restrict__ bt) {
    int idx = blockIdx.x * 256 + threadIdx.x;      // float4 index
    int b = idx >> 14;                              // 16384 float4 per batch
    int r = idx & 16383;
    int node = 63 + (r >> 8);
    int d0 = (r & 255) * 4;
    const float4 v = *reinterpret_cast<const float4*>(
        g_states + ((size_t)b * NN + node) * DD + d0);
    const float4 t = *reinterpret_cast<const float4*>(bt + 6 * DD + d0);
    if (v.x > t.x || v.y > t.y || v.z > t.z || v.w > t.w)
        g_any6 = 1;                                 // race-benign: all writers store 1
}

// ---------------------------------------------------------------------------
// Tail: levels 5..0. If no L6 value passed its threshold, all remaining levels
// are exactly zero (states pre-zeroed by prep) -> return immediately.
// Rare path: compute levels sequentially with grid barriers (NT blocks, all
// resident), full-K, plain stores.
// ---------------------------------------------------------------------------
__device__ __forceinline__ void tail_barrier() {
    __syncthreads();
    if (threadIdx.x == 0) {
        __threadfence();
        unsigned gen = g_bar_gen;
        unsigned old = atomicAdd(&g_bar_cnt, 1);
        if (old == NT - 1) {
            g_bar_cnt = 0;
            __threadfence();
            g_bar_gen = gen + 1;
        } else {
            while (g_bar_gen == gen) { __nanosleep(64); }
        }
    }
    __syncthreads();
}

__global__ void __launch_bounds__(128) tree_tail_kernel(const float* __restrict__ W,
                                                        const float* __restrict__ bt) {
    if (g_any6 == 0) return;                 // expected path: everything below L6 is zero

    __shared__ float As[2][64 * SST];
    __shared__ float Bs[2][64 * SST];
    __shared__ float tb[2][32];

    int tid = threadIdx.x;
    int warp = tid >> 5, lane = tid & 31;
    int wm = warp >> 1, wn = warp & 1;
    int g = lane >> 2, t4 = lane & 3;

    for (int level = 5; level >= 0; --level) {
        int NL = 1 << level;
        int ls = NL - 1;
        int Mtot = NL * 4;
        int mblocks = (Mtot + 63) >> 6;
        int ntiles = mblocks * 16;
        const float* btc = bt + (size_t)(level + 1) * DD;

        for (int t = blockIdx.x; t < ntiles; t += NT) {
            int m0 = (t >> 4) * 64;
            int n0 = (t & 15) * 64;

            float acc[2][4][4];
            ZERO_ACC();
            KLOOP(0, 64);

#pragma unroll
            for (int i = 0; i < 2; i++) {
                int rg = m0 + wm * 32 + i * 16 + g;
#pragma unroll
                for (int j = 0; j < 4; j++) {
                    int col = n0 + wn * 32 + j * 8 + t4 * 2;
                    if (rg < Mtot) {
                        int bb = rg >> level, jj = rg & (NL - 1);
                        float* Crow = g_states + ((size_t)bb * NN + ls + jj) * DD;
                        Crow[col]     = acc[i][j][0];
                        Crow[col + 1] = acc[i][j][1];
                    }
                    int rg8 = rg + 8;
                    if (rg8 < Mtot) {
                        int bb = rg8 >> level, jj = rg8 & (NL - 1);
                        float* Crow = g_states + ((size_t)bb * NN + ls + jj) * DD;
                        Crow[col]     = acc[i][j][2];
                        Crow[col + 1] = acc[i][j][3];
                    }
                }
            }
        }
        tail_barrier();
    }
}

// ---------------------------------------------------------------------------
// Mixture, two-stage, lazy spike threshold per node level.
// ---------------------------------------------------------------------------
__global__ void __launch_bounds__(512) mixture1_kernel(const float* __restrict__ nw,
                                                       const float* __restrict__ bt) {
    int ld = threadIdx.x & 31;
    int ln = threadIdx.x >> 5;
    int d  = blockIdx.x * 32 + ld;
    int sp = blockIdx.y;
    int nend = sp * 128 + 128;
    if (nend > NN) nend = NN;
    float Z = 0.f, a0 = 0.f, a1 = 0.f, a2 = 0.f, a3 = 0.f;
    for (int n = sp * 128 + ln; n < nend; n += 16) {
        float e = __expf(nw[n * DD + d]);
        float v0 = g_states[((size_t)0 * NN + n) * DD + d];
        float v1 = g_states[((size_t)1 * NN + n) * DD + d];
        float v2 = g_states[((size_t)2 * NN + n) * DD + d];
        float v3 = g_states[((size_t)3 * NN + n) * DD + d];
        if (n < 511) {
            int lv = 31 - __clz(n + 1);
            float thr = bt[lv * DD + d];
            v0 = v0 > thr ? v0 : 0.f;
            v1 = v1 > thr ? v1 : 0.f;
            v2 = v2 > thr ? v2 : 0.f;
            v3 = v3 > thr ? v3 : 0.f;
        }
        Z += e;
        a0 += e * v0; a1 += e * v1; a2 += e * v2; a3 += e * v3;
    }
    __shared__ float red[5][16][32];
    red[0][ln][ld] = Z;  red[1][ln][ld] = a0; red[2][ln][ld] = a1;
    red[3][ln][ld] = a2; red[4][ln][ld] = a3;
    __syncthreads();
    if (ln == 0) {
        float v[5];
#pragma unroll
        for (int k = 0; k < 5; k++) {
            float s = 0.f;
#pragma unroll
            for (int i = 0; i < 16; i++) s += red[k][i][ld];
            v[k] = s;
        }
#pragma unroll
        for (int k = 0; k < 5; k++) g_mixpart[sp][k][d] = v[k];
    }
}

__global__ void __launch_bounds__(256) mixture2_kernel() {
    int d = blockIdx.x * 256 + threadIdx.x;
    float Z = 0.f, a0 = 0.f, a1 = 0.f, a2 = 0.f, a3 = 0.f;
#pragma unroll
    for (int sp = 0; sp < 8; sp++) {
        Z  += g_mixpart[sp][0][d];
        a0 += g_mixpart[sp][1][d];
        a1 += g_mixpart[sp][2][d];
        a2 += g_mixpart[sp][3][d];
        a3 += g_mixpart[sp][4][d];
    }
    float inv = 1.f / Z;
    g_mixture[0 * DD + d] = a0 * inv;
    g_mixture[1 * DD + d] = a1 * inv;
    g_mixture[2 * DD + d] = a2 * inv;
    g_mixture[3 * DD + d] = a3 * inv;
}

// ---------------------------------------------------------------------------
// Final: out = RMSNorm(x + mixture[b]) * rms_w, 8 rows per block.
// ---------------------------------------------------------------------------
__global__ void __launch_bounds__(256) final_kernel(const float* __restrict__ x,
                                                    const float* __restrict__ rms_w,
                                                    float* __restrict__ out) {
    int blk = blockIdx.x;
    int b  = blk >> 10;
    int t0 = (blk & 1023) * 8;
    int tid = threadIdx.x;
    int lane = tid & 31, warp = tid >> 5;

    __shared__ float4 smix[256];
    __shared__ float4 srw[256];
    __shared__ float  sred[8];

    smix[tid] = reinterpret_cast<const float4*>(g_mixture + b * DD)[tid];
    srw[tid]  = reinterpret_cast<const float4*>(rms_w)[tid];
    __syncthreads();
    float4 mix = smix[tid], rw = srw[tid];

    const float4* xb = reinterpret_cast<const float4*>(x) + ((size_t)(b * TT + t0)) * 256;
    float4*       ob = reinterpret_cast<float4*>(out)     + ((size_t)(b * TT + t0)) * 256;

    for (int r = 0; r < 8; r++) {
        float4 v = xb[(size_t)r * 256 + tid];
        v.x += mix.x; v.y += mix.y; v.z += mix.z; v.w += mix.w;
        float ss = v.x * v.x + v.y * v.y + v.z * v.z + v.w * v.w;
#pragma unroll
        for (int o = 16; o > 0; o >>= 1) ss += __shfl_xor_sync(0xffffffffu, ss, o);
        __syncthreads();
        if (lane == 0) sred[warp] = ss;
        __syncthreads();
        float tot = 0.f;
#pragma unroll
        for (int i = 0; i < 8; i++) tot += sred[i];
        float inv = rsqrtf(tot * (1.0f / 1024.0f) + 1.1920929e-7f);
        float4 o4;
        o4.x = v.x * rw.x * inv; o4.y = v.y * rw.y * inv;
        o4.z = v.z * rw.z * inv; o4.w = v.w * rw.w * inv;
        ob[(size_t)r * 256 + tid] = o4;
    }
}

// ---------------------------------------------------------------------------
// launch: prep -> L8 -> L7 -> L6 (split-K) -> flag scan -> tail (usually no-op)
//         -> mixture1 -> mixture2 -> final   (9 launches)
// ---------------------------------------------------------------------------
extern "C" void kernel_launch(void* const* d_in, const int* in_sizes, int n_in,
                              void* d_out, int out_size) {
    const float* x     = (const float*)d_in[0];
    const float* W     = (const float*)d_in[1];
    const float* nw    = (const float*)d_in[2];
    const float* bt    = (const float*)d_in[3];
    const float* rms_w = (const float*)d_in[5];   // as_w (d_in[4]) unused (×0.0)
    float* out = (float*)d_out;

    prep_kernel<<<4092, 256>>>(x);

    // L8: M=1024, S=4, A = leaves (no threshold)
    tree_gemm2_kernel<<<dim3(16, 16, 4), 128>>>(W, nullptr, 8, 255, 256, 512);
    // L7: M=512, S=4, children thresholds bt[8]
    tree_gemm2_kernel<<<dim3(8, 16, 4), 128>>>(W, bt + 8 * DD, 7, 127, 128, 512);
    // L6: M=256, S=8, children thresholds bt[7]
    tree_gemm2_kernel<<<dim3(4, 16, 8), 128>>>(W, bt + 7 * DD, 6, 63, 64, 256);
    // flag scan over L6 raw states (sets g_any6)
    l6_flag_kernel<<<256, 256>>>(bt);
    // L5..L0: early-exit when L6 produced no spikes (the expected case)
    tree_tail_kernel<<<NT, 128>>>(W, bt);

    mixture1_kernel<<<dim3(32, 8), 512>>>(nw, bt);
    mixture2_kernel<<<4, 256>>>();
    final_kernel<<<4096, 256>>>(x, rms_w, out);
}